// round 6
// baseline (speedup 1.0000x reference)
#include <cuda_runtime.h>
#include <math.h>

// B=2048, T=64, IN=8, HID=6 qubits, OUT=8, NLAYERS=2, concat=16
#define NB    2048
#define NT    64
#define NIN   8
#define NHID  6
#define NOUT  8
#define NCAT  16
#define NLAY  2

__device__ __forceinline__ float sigmoidf_(float v) {
    return 1.0f / (1.0f + __expf(-v));
}
__device__ __forceinline__ float tanhfast_(float v) {
    return 2.0f / (1.0f + __expf(-2.0f * v)) - 1.0f;
}

// Layout: ONE warp = ONE batch element. The 4 octets (8-lane groups) evolve
// the same element's state through the 4 gate circuits (f,i,g,o = octet id).
// 6-qubit amp index bits: wires 0,1,2 -> lane bits 2,1,0 (within octet);
// wires 3,4,5 -> in-thread amp bits 2,1,0. 8 complex amps per thread.
// One shuffle instruction serves all 4 gate circuits simultaneously.
__global__ __launch_bounds__(256) void qlstm_kernel(
    const float* __restrict__ x,      // [B, T, IN]
    const float* __restrict__ W_in,   // [HID, 16]
    const float* __restrict__ b_in,   // [HID]
    const float* __restrict__ W_out,  // [OUT, HID]
    const float* __restrict__ b_out,  // [OUT]
    const float* __restrict__ wf,     // [NLAY, HID]
    const float* __restrict__ wi,
    const float* __restrict__ wg,
    const float* __restrict__ wo,
    float* __restrict__ out)          // [B, T, OUT]
{
    __shared__ float2 sCS[4][NLAY][NHID];   // (cos, sin) of 0.5*weight

    const int tid = threadIdx.x;
    if (tid < 4 * NLAY * NHID) {
        const float* wp[4] = {wf, wi, wg, wo};
        int g = tid / (NLAY * NHID);
        int r = tid % (NLAY * NHID);
        float s_, c_;
        sincosf(0.5f * wp[g][r], &s_, &c_);
        sCS[g][r / NHID][r % NHID] = make_float2(c_, s_);
    }
    __syncthreads();

    const unsigned FULL = 0xffffffffu;
    const int lane = tid & 31;
    const int b    = blockIdx.x * (blockDim.x >> 5) + (tid >> 5);  // element
    const int oct  = lane >> 3;            // gate id (f,i,g,o)
    const int q    = lane & 7;             // wire0,1,2 = q bits 2,1,0

    // Hoisted weights
    float win[NCAT];
    float ybias;
    {
        int row = (lane < NHID) ? lane : 0;
        #pragma unroll
        for (int j = 0; j < NCAT; j++) win[j] = W_in[row * NCAT + j];
        ybias = b_in[row];
    }
    float wrow[NHID];
    #pragma unroll
    for (int w = 0; w < NHID; w++) wrow[w] = W_out[q * NHID + w];
    const float bj = b_out[q];

    const bool bx0 = (q >> 2) & 1;   // wire0 bit
    const bool bx1 = (q >> 1) & 1;   // wire1 bit
    const bool bx2 = q & 1;          // wire2 bit
    const bool c23 = bx2;            // CNOT(2,3) ctrl
    const int  pl  = __popc(q);      // lane popcount (embedding phase)

    // Fused CNOT(0,1)∘CNOT(1,2) source lane within octet
    int qp = q ^ ((q >> 1) & 1);          // C12: flip bit0 if bit1
    qp ^= ((qp >> 2) & 1) << 1;           // C01: flip bit1 if bit2
    const int fsrc = (lane & 24) | qp;

    // Per-layer (cos,sin) pairs for this octet's gate circuit
    float2 cs_[NLAY][NHID];
    #pragma unroll
    for (int l = 0; l < NLAY; l++)
        #pragma unroll
        for (int w = 0; w < NHID; w++) cs_[l][w] = sCS[oct][l][w];

    const float* xrow = x + (size_t)b * NT * NIN;
    float* orow = out + (size_t)b * NT * NOUT;

    float h = 0.0f, c = 0.0f;

    #pragma unroll 1
    for (int t = 0; t < NT; t++) {
        // ---- y = [h, x_t] @ W_in^T + b_in ----
        float v = (lane < 8) ? h : ((lane < 16) ? xrow[t * NIN + (lane - 8)] : 0.0f);
        float y = ybias;
        #pragma unroll
        for (int j = 0; j < NCAT; j++) {
            float vj = __shfl_sync(FULL, v, j);
            y = fmaf(win[j], vj, y);
        }
        float myS, myC;
        __sincosf(0.5f * y, &myS, &myC);
        float cw[NHID], sw[NHID];
        #pragma unroll
        for (int w = 0; w < NHID; w++) {
            cw[w] = __shfl_sync(FULL, myC, w);
            sw[w] = __shfl_sync(FULL, myS, w);
        }

        // ---- embedding state in closed form (product state) ----
        // amp(x) = (-i)^popc(x) * prod_w (x_w ? s_w : c_w)
        float gr[8], gi[8];
        {
            float lp = (bx0 ? sw[0] : cw[0]) * (bx1 ? sw[1] : cw[1])
                     * (bx2 ? sw[2] : cw[2]);
            float c34 = cw[3] * cw[4], c3s4 = cw[3] * sw[4];
            float s34 = sw[3] * cw[4], s3s4 = sw[3] * sw[4];
            float ap[8];
            ap[0] = c34  * cw[5]; ap[1] = c34  * sw[5];
            ap[2] = c3s4 * cw[5]; ap[3] = c3s4 * sw[5];
            ap[4] = s34  * cw[5]; ap[5] = s34  * sw[5];
            ap[6] = s3s4 * cw[5]; ap[7] = s3s4 * sw[5];
            #pragma unroll
            for (int a = 0; a < 8; a++) {
                float m = lp * ap[a];
                int k = (pl + __popc(a)) & 3;   // (-i)^k
                gr[a] = (k == 0) ? m : ((k == 2) ? -m : 0.0f);
                gi[a] = (k == 1) ? -m : ((k == 3) ? m : 0.0f);
            }
        }

        // ---- entangler layers (each octet applies its own gate's weights) ----
        #pragma unroll
        for (int l = 0; l < NLAY; l++) {
            // RX, lane wires 0..2 (shfl masks 4,2,1)
            #pragma unroll
            for (int w = 0; w < 3; w++) {
                const int m = 4 >> w;
                float2 cs = cs_[l][w];
                #pragma unroll
                for (int a = 0; a < 8; a++) {
                    float pr = __shfl_xor_sync(FULL, gr[a], m);
                    float pi = __shfl_xor_sync(FULL, gi[a], m);
                    gr[a] = fmaf(cs.x, gr[a], cs.y * pi);
                    gi[a] = fmaf(cs.x, gi[a], -cs.y * pr);
                }
            }
            // RX, in-thread wires 3..5 (amp masks 4,2,1)
            #pragma unroll
            for (int w = 3; w < 6; w++) {
                const int m = 4 >> (w - 3);
                float2 cs = cs_[l][w];
                float nr[8], ni[8];
                #pragma unroll
                for (int a = 0; a < 8; a++) {
                    nr[a] = fmaf(cs.x, gr[a], cs.y * gi[a ^ m]);
                    ni[a] = fmaf(cs.x, gi[a], -cs.y * gr[a ^ m]);
                }
                #pragma unroll
                for (int a = 0; a < 8; a++) { gr[a] = nr[a]; gi[a] = ni[a]; }
            }
            if (l != NLAY - 1) {
                // Fused CNOT(0,1)+CNOT(1,2): one lane permutation
                #pragma unroll
                for (int a = 0; a < 8; a++) {
                    gr[a] = __shfl_sync(FULL, gr[a], fsrc);
                    gi[a] = __shfl_sync(FULL, gi[a], fsrc);
                }
                // CNOT(2,3): ctrl lane bit0, tgt amp bit2 (cond swap)
                #pragma unroll
                for (int a = 0; a < 4; a++) {
                    float tr = gr[a], ti = gi[a];
                    gr[a]     = c23 ? gr[a + 4] : gr[a];
                    gi[a]     = c23 ? gi[a + 4] : gi[a];
                    gr[a + 4] = c23 ? tr : gr[a + 4];
                    gi[a + 4] = c23 ? ti : gi[a + 4];
                }
                // CNOT(3,4): swap (4,6),(5,7); CNOT(4,5): swap (2,3),(6,7)
                {
                    float tr;
                    tr = gr[4]; gr[4] = gr[6]; gr[6] = tr;
                    tr = gi[4]; gi[4] = gi[6]; gi[6] = tr;
                    tr = gr[5]; gr[5] = gr[7]; gr[7] = tr;
                    tr = gi[5]; gi[5] = gi[7]; gi[7] = tr;
                    tr = gr[2]; gr[2] = gr[3]; gr[3] = tr;
                    tr = gi[2]; gi[2] = gi[3]; gi[3] = tr;
                    tr = gr[6]; gr[6] = gr[7]; gr[7] = tr;
                    tr = gi[6]; gi[6] = gi[7]; gi[7] = tr;
                }
                // CNOT(5,0): odd amps exchange across lane mask 4
                #pragma unroll
                for (int a = 1; a < 8; a += 2) {
                    gr[a] = __shfl_xor_sync(FULL, gr[a], 4);
                    gi[a] = __shfl_xor_sync(FULL, gi[a], 4);
                }
            }
            // Last layer: CNOT ring elided; folded into expval signs below.
        }

        // ---- expvals (perm-folded signs) + output linear ----
        // Four independent butterfly chains (A, A3, A4, A5) interleaved per
        // offset so the scheduler sees 4 concurrent SHFL chains.
        float acc;
        {
            float p[8];
            #pragma unroll
            for (int a = 0; a < 8; a++)
                p[a] = fmaf(gr[a], gr[a], gi[a] * gi[a]);
            float t01 = p[0] + p[1], t23 = p[2] + p[3];
            float t45 = p[4] + p[5], t67 = p[6] + p[7];
            float slo = t01 + t23, shi = t45 + t67;
            float uA  = slo + shi;
            float u3  = slo - shi;
            float u4  = (t01 + t67) - (t23 + t45);
            float u5  = ((p[0] + p[3]) + (p[5] + p[6]))
                      - ((p[1] + p[2]) + (p[4] + p[7]));

            // offset-4 stage (A, A3, A4 over x0; A5 starts at offset 2)
            float tA = __shfl_xor_sync(FULL, uA, 4);
            float t3 = __shfl_xor_sync(FULL, u3, 4);
            float t4 = __shfl_xor_sync(FULL, u4, 4);
            float t5 = __shfl_xor_sync(FULL, u5, 2);
            uA = bx0 ? tA - uA : uA - tA;
            u3 = bx0 ? t3 - u3 : u3 - t3;
            u4 = bx0 ? t4 - u4 : u4 - t4;
            u5 = bx1 ? t5 - u5 : u5 - t5;
            // offset-2 stage (A, A3, A4); A5 offset-1
            tA = __shfl_xor_sync(FULL, uA, 2);
            t3 = __shfl_xor_sync(FULL, u3, 2);
            t4 = __shfl_xor_sync(FULL, u4, 2);
            t5 = __shfl_xor_sync(FULL, u5, 1);
            uA = bx1 ? tA - uA : uA - tA;
            u3 = bx1 ? t3 - u3 : u3 - t3;
            u4 = bx1 ? t4 - u4 : u4 - t4;
            u5 = bx2 ? t5 - u5 : u5 - t5;
            // offset-1 stage (A, A3, A4); A5 offset-4
            tA = __shfl_xor_sync(FULL, uA, 1);
            t3 = __shfl_xor_sync(FULL, u3, 1);
            t4 = __shfl_xor_sync(FULL, u4, 1);
            t5 = __shfl_xor_sync(FULL, u5, 4);
            float E1 = uA + tA;
            float E2 = bx2 ? tA - uA : uA - tA;
            float E3 = bx2 ? t3 - u3 : u3 - t3;
            float E4 = bx2 ? t4 - u4 : u4 - t4;
            float E0 = u5 + t5;
            float E5 = bx0 ? t5 - u5 : u5 - t5;

            acc = bj;
            acc = fmaf(wrow[0], E0, acc);
            acc = fmaf(wrow[1], E1, acc);
            acc = fmaf(wrow[2], E2, acc);
            acc = fmaf(wrow[3], E3, acc);
            acc = fmaf(wrow[4], E4, acc);
            acc = fmaf(wrow[5], E5, acc);
        }

        // ---- gather all 4 gates for dim q (every lane gets all four) ----
        float af = __shfl_sync(FULL, acc, q);        // octet 0 = f
        float ai = __shfl_sync(FULL, acc, 8 | q);    // octet 1 = i
        float ag = __shfl_sync(FULL, acc, 16 | q);   // octet 2 = g
        float ao = __shfl_sync(FULL, acc, 24 | q);   // octet 3 = o

        float fg = sigmoidf_(af);
        float ig = sigmoidf_(ai);
        float gg = tanhfast_(ag);
        float og = sigmoidf_(ao);
        c = fmaf(fg, c, ig * gg);
        h = og * tanhfast_(c);

        if (lane < NOUT) orow[t * NOUT + q] = h;
    }
}

extern "C" void kernel_launch(void* const* d_in, const int* in_sizes, int n_in,
                              void* d_out, int out_size) {
    (void)in_sizes; (void)n_in; (void)out_size;
    // 1 element/warp, 8 warps/block -> 8 elements/block, 256 blocks, 2048 warps
    qlstm_kernel<<<NB / 8, 256>>>(
        (const float*)d_in[0],   // x
        (const float*)d_in[1],   // W_in
        (const float*)d_in[2],   // b_in
        (const float*)d_in[3],   // W_out
        (const float*)d_in[4],   // b_out
        (const float*)d_in[5],   // wf
        (const float*)d_in[6],   // wi
        (const float*)d_in[7],   // wg
        (const float*)d_in[8],   // wo
        (float*)d_out);
}

// round 8
// speedup vs baseline: 1.1488x; 1.1488x over previous
#include <cuda_runtime.h>
#include <math.h>

// B=2048, T=64, IN=8, HID=6 qubits, OUT=8, NLAYERS=2, concat=16
#define NB    2048
#define NT    64
#define NIN   8
#define NHID  6
#define NOUT  8
#define NCAT  16
#define NLAY  2

// Precomputed x-part of the input linear: xpre[b][t][w] = b_in[w] + W_x[w]·x[b,t]
__device__ float g_xpre[NB * NT * NHID];

__device__ __forceinline__ float sigmoidf_(float v) {
    return 1.0f / (1.0f + __expf(-v));
}
__device__ __forceinline__ float tanhfast_(float v) {
    return 2.0f / (1.0f + __expf(-2.0f * v)) - 1.0f;
}

// Prepass: one thread per (b,t); computes the 6 x-dependent partial angles.
__global__ __launch_bounds__(256) void xpre_kernel(
    const float* __restrict__ x,      // [B, T, IN]
    const float* __restrict__ W_in,   // [HID, 16]  (cols 8..15 = x part)
    const float* __restrict__ b_in)   // [HID]
{
    int idx = blockIdx.x * blockDim.x + threadIdx.x;   // b*NT + t
    if (idx >= NB * NT) return;
    float4 xa = *reinterpret_cast<const float4*>(x + (size_t)idx * NIN);
    float4 xb = *reinterpret_cast<const float4*>(x + (size_t)idx * NIN + 4);
    #pragma unroll
    for (int w = 0; w < NHID; w++) {
        const float* wr = W_in + w * NCAT + 8;
        float acc = b_in[w];
        acc = fmaf(wr[0], xa.x, acc);
        acc = fmaf(wr[1], xa.y, acc);
        acc = fmaf(wr[2], xa.z, acc);
        acc = fmaf(wr[3], xa.w, acc);
        acc = fmaf(wr[4], xb.x, acc);
        acc = fmaf(wr[5], xb.y, acc);
        acc = fmaf(wr[6], xb.z, acc);
        acc = fmaf(wr[7], xb.w, acc);
        g_xpre[idx * NHID + w] = acc;
    }
}

// Layout: ONE warp = ONE batch element. The 4 octets (8-lane groups) evolve
// the same element's state through the 4 gate circuits (f,i,g,o = octet id).
// Wires 0,1,2 -> lane bits 2,1,0 (within octet); wires 3,4,5 -> in-thread
// amp bits 2,1,0. 8 complex amps per thread.
// Circuit folding:
//  - Embedding RX(y) + layer-1 RX(th1) merged: product state with angle y+th1.
//  - Final CNOT ring elided; permutation folded into expval signs.
__global__ __launch_bounds__(256) void qlstm_kernel(
    const float* __restrict__ W_in,   // [HID, 16] (cols 0..7 = h part)
    const float* __restrict__ W_out,  // [OUT, HID]
    const float* __restrict__ b_out,  // [OUT]
    const float* __restrict__ wf,     // [NLAY, HID]
    const float* __restrict__ wi,
    const float* __restrict__ wg,
    const float* __restrict__ wo,
    float* __restrict__ out)          // [B, T, OUT]
{
    __shared__ float2 sCS[4][NLAY][NHID];   // (cos, sin) of 0.5*weight

    const int tid = threadIdx.x;
    if (tid < 4 * NLAY * NHID) {
        const float* wp[4] = {wf, wi, wg, wo};
        int g = tid / (NLAY * NHID);
        int r = tid % (NLAY * NHID);
        float s_, c_;
        sincosf(0.5f * wp[g][r], &s_, &c_);
        sCS[g][r / NHID][r % NHID] = make_float2(c_, s_);
    }
    __syncthreads();

    const unsigned FULL = 0xffffffffu;
    const int lane = tid & 31;
    const int b    = blockIdx.x * (blockDim.x >> 5) + (tid >> 5);  // element
    const int oct  = lane >> 3;            // gate id (f,i,g,o)
    const int q    = lane & 7;             // wire0,1,2 = q bits 2,1,0

    // Hoisted weights: h-part row of W_in (8 cols) for this lane's angle row
    float winh[8];
    {
        int row = (lane < NHID) ? lane : 0;
        #pragma unroll
        for (int j = 0; j < 8; j++) winh[j] = W_in[row * NCAT + j];
    }
    float wrow[NHID];
    #pragma unroll
    for (int w = 0; w < NHID; w++) wrow[w] = W_out[q * NHID + w];
    const float bj = b_out[q];

    const bool bx0 = (q >> 2) & 1;   // wire0 bit
    const bool bx1 = (q >> 1) & 1;   // wire1 bit
    const bool bx2 = q & 1;          // wire2 bit
    const bool c23 = bx2;            // CNOT(2,3) ctrl
    const int  pl  = __popc(q);      // lane popcount (product-state phase)

    // Fused CNOT(0,1)∘CNOT(1,2) source lane within octet
    int qp = q ^ ((q >> 1) & 1);          // C12: flip bit0 if bit1
    qp ^= ((qp >> 2) & 1) << 1;           // C01: flip bit1 if bit2
    const int fsrc = (lane & 24) | qp;

    // Per-layer (cos,sin) pairs for this octet's gate circuit
    float2 cs1[NHID], cs2[NHID];
    #pragma unroll
    for (int w = 0; w < NHID; w++) { cs1[w] = sCS[oct][0][w]; cs2[w] = sCS[oct][1][w]; }

    float* orow = out + (size_t)b * NT * NOUT;
    const float* prep = g_xpre + (size_t)b * NT * NHID;

    float h = 0.0f, c = 0.0f;
    float pre_cur = (lane < NHID) ? prep[lane] : 0.0f;

    #pragma unroll 1
    for (int t = 0; t < NT; t++) {
        // ---- y = pre + W_h·h (h on lanes 0..7) ----
        float y = pre_cur;
        #pragma unroll
        for (int j = 0; j < 8; j++) {
            float hj = __shfl_sync(FULL, h, j);
            y = fmaf(winh[j], hj, y);
        }
        // prefetch next step's precomputed angles (overlaps whole step)
        float pre_nxt = 0.0f;
        if (t + 1 < NT && lane < NHID) pre_nxt = prep[(t + 1) * NHID + lane];

        float myS, myC;
        __sincosf(0.5f * y, &myS, &myC);
        float cay[NHID], say[NHID];
        #pragma unroll
        for (int w = 0; w < NHID; w++) {
            cay[w] = __shfl_sync(FULL, myC, w);
            say[w] = __shfl_sync(FULL, myS, w);
        }

        // ---- merged angles: RX(y_w) ∘ RX(th1_w) = RX(y_w + th1_w) ----
        float cw[NHID], sw[NHID];
        #pragma unroll
        for (int w = 0; w < NHID; w++) {
            cw[w] = cay[w] * cs1[w].x - say[w] * cs1[w].y;
            sw[w] = fmaf(say[w], cs1[w].x, cay[w] * cs1[w].y);
        }

        // ---- product state (embedding + layer-1 RX) in closed form ----
        // amp(x) = (-i)^popc(x) * prod_w (x_w ? s_w : c_w)
        float gr[8], gi[8];
        {
            float lp = (bx0 ? sw[0] : cw[0]) * (bx1 ? sw[1] : cw[1])
                     * (bx2 ? sw[2] : cw[2]);
            float c34 = cw[3] * cw[4], c3s4 = cw[3] * sw[4];
            float s34 = sw[3] * cw[4], s3s4 = sw[3] * sw[4];
            float ap[8];
            ap[0] = c34  * cw[5]; ap[1] = c34  * sw[5];
            ap[2] = c3s4 * cw[5]; ap[3] = c3s4 * sw[5];
            ap[4] = s34  * cw[5]; ap[5] = s34  * sw[5];
            ap[6] = s3s4 * cw[5]; ap[7] = s3s4 * sw[5];
            #pragma unroll
            for (int a = 0; a < 8; a++) {
                float m = lp * ap[a];
                int k = (pl + __popc(a)) & 3;   // (-i)^k
                gr[a] = (k == 0) ? m : ((k == 2) ? -m : 0.0f);
                gi[a] = (k == 1) ? -m : ((k == 3) ? m : 0.0f);
            }
        }

        // ---- CNOT ring #1 ----
        // Fused CNOT(0,1)+CNOT(1,2): one lane permutation
        #pragma unroll
        for (int a = 0; a < 8; a++) {
            gr[a] = __shfl_sync(FULL, gr[a], fsrc);
            gi[a] = __shfl_sync(FULL, gi[a], fsrc);
        }
        // CNOT(2,3): ctrl lane bit0, tgt amp bit2 (cond swap)
        #pragma unroll
        for (int a = 0; a < 4; a++) {
            float tr = gr[a], ti = gi[a];
            gr[a]     = c23 ? gr[a + 4] : gr[a];
            gi[a]     = c23 ? gi[a + 4] : gi[a];
            gr[a + 4] = c23 ? tr : gr[a + 4];
            gi[a + 4] = c23 ? ti : gi[a + 4];
        }
        // CNOT(3,4): swap (4,6),(5,7); CNOT(4,5): swap (2,3),(6,7)
        {
            float tr;
            tr = gr[4]; gr[4] = gr[6]; gr[6] = tr;
            tr = gi[4]; gi[4] = gi[6]; gi[6] = tr;
            tr = gr[5]; gr[5] = gr[7]; gr[7] = tr;
            tr = gi[5]; gi[5] = gi[7]; gi[7] = tr;
            tr = gr[2]; gr[2] = gr[3]; gr[3] = tr;
            tr = gi[2]; gi[2] = gi[3]; gi[3] = tr;
            tr = gr[6]; gr[6] = gr[7]; gr[7] = tr;
            tr = gi[6]; gi[6] = gi[7]; gi[7] = tr;
        }
        // CNOT(5,0): odd amps exchange across lane mask 4
        #pragma unroll
        for (int a = 1; a < 8; a += 2) {
            gr[a] = __shfl_xor_sync(FULL, gr[a], 4);
            gi[a] = __shfl_xor_sync(FULL, gi[a], 4);
        }

        // ---- RX layer 2 ----
        #pragma unroll
        for (int w = 0; w < 3; w++) {          // lane wires (masks 4,2,1)
            const int m = 4 >> w;
            float2 cs = cs2[w];
            #pragma unroll
            for (int a = 0; a < 8; a++) {
                float pr = __shfl_xor_sync(FULL, gr[a], m);
                float pi = __shfl_xor_sync(FULL, gi[a], m);
                gr[a] = fmaf(cs.x, gr[a], cs.y * pi);
                gi[a] = fmaf(cs.x, gi[a], -cs.y * pr);
            }
        }
        #pragma unroll
        for (int w = 3; w < 6; w++) {          // in-thread wires (amp masks 4,2,1)
            const int m = 4 >> (w - 3);
            float2 cs = cs2[w];
            float nr[8], ni[8];
            #pragma unroll
            for (int a = 0; a < 8; a++) {
                nr[a] = fmaf(cs.x, gr[a], cs.y * gi[a ^ m]);
                ni[a] = fmaf(cs.x, gi[a], -cs.y * gr[a ^ m]);
            }
            #pragma unroll
            for (int a = 0; a < 8; a++) { gr[a] = nr[a]; gi[a] = ni[a]; }
        }
        // Final CNOT ring elided; folded into expval signs below.

        // ---- expvals (perm-folded signs) + output linear ----
        float acc;
        {
            float p[8];
            #pragma unroll
            for (int a = 0; a < 8; a++)
                p[a] = fmaf(gr[a], gr[a], gi[a] * gi[a]);
            float t01 = p[0] + p[1], t23 = p[2] + p[3];
            float t45 = p[4] + p[5], t67 = p[6] + p[7];
            float slo = t01 + t23, shi = t45 + t67;
            float uA  = slo + shi;
            float u3  = slo - shi;
            float u4  = (t01 + t67) - (t23 + t45);
            float u5  = ((p[0] + p[3]) + (p[5] + p[6]))
                      - ((p[1] + p[2]) + (p[4] + p[7]));

            // four interleaved butterfly chains
            float tA = __shfl_xor_sync(FULL, uA, 4);
            float t3 = __shfl_xor_sync(FULL, u3, 4);
            float t4 = __shfl_xor_sync(FULL, u4, 4);
            float t5 = __shfl_xor_sync(FULL, u5, 2);
            uA = bx0 ? tA - uA : uA - tA;
            u3 = bx0 ? t3 - u3 : u3 - t3;
            u4 = bx0 ? t4 - u4 : u4 - t4;
            u5 = bx1 ? t5 - u5 : u5 - t5;
            tA = __shfl_xor_sync(FULL, uA, 2);
            t3 = __shfl_xor_sync(FULL, u3, 2);
            t4 = __shfl_xor_sync(FULL, u4, 2);
            t5 = __shfl_xor_sync(FULL, u5, 1);
            uA = bx1 ? tA - uA : uA - tA;
            u3 = bx1 ? t3 - u3 : u3 - t3;
            u4 = bx1 ? t4 - u4 : u4 - t4;
            u5 = bx2 ? t5 - u5 : u5 - t5;
            tA = __shfl_xor_sync(FULL, uA, 1);
            t3 = __shfl_xor_sync(FULL, u3, 1);
            t4 = __shfl_xor_sync(FULL, u4, 1);
            t5 = __shfl_xor_sync(FULL, u5, 4);
            float E1 = uA + tA;
            float E2 = bx2 ? tA - uA : uA - tA;
            float E3 = bx2 ? t3 - u3 : u3 - t3;
            float E4 = bx2 ? t4 - u4 : u4 - t4;
            float E0 = u5 + t5;
            float E5 = bx0 ? t5 - u5 : u5 - t5;

            acc = bj;
            acc = fmaf(wrow[0], E0, acc);
            acc = fmaf(wrow[1], E1, acc);
            acc = fmaf(wrow[2], E2, acc);
            acc = fmaf(wrow[3], E3, acc);
            acc = fmaf(wrow[4], E4, acc);
            acc = fmaf(wrow[5], E5, acc);
        }

        // ---- gather all 4 gates for dim q ----
        float af = __shfl_sync(FULL, acc, q);        // octet 0 = f
        float ai = __shfl_sync(FULL, acc, 8 | q);    // octet 1 = i
        float ag = __shfl_sync(FULL, acc, 16 | q);   // octet 2 = g
        float ao = __shfl_sync(FULL, acc, 24 | q);   // octet 3 = o

        float fg = sigmoidf_(af);
        float ig = sigmoidf_(ai);
        float gg = tanhfast_(ag);
        float og = sigmoidf_(ao);
        c = fmaf(fg, c, ig * gg);
        h = og * tanhfast_(c);

        if (lane < NOUT) orow[t * NOUT + q] = h;
        pre_cur = pre_nxt;
    }
}

extern "C" void kernel_launch(void* const* d_in, const int* in_sizes, int n_in,
                              void* d_out, int out_size) {
    (void)in_sizes; (void)n_in; (void)out_size;
    xpre_kernel<<<(NB * NT + 255) / 256, 256>>>(
        (const float*)d_in[0],   // x
        (const float*)d_in[1],   // W_in
        (const float*)d_in[2]);  // b_in
    // 1 element/warp, 8 warps/block -> 256 blocks, 2048 warps
    qlstm_kernel<<<NB / 8, 256>>>(
        (const float*)d_in[1],   // W_in (h part)
        (const float*)d_in[3],   // W_out
        (const float*)d_in[4],   // b_out
        (const float*)d_in[5],   // wf
        (const float*)d_in[6],   // wi
        (const float*)d_in[7],   // wg
        (const float*)d_in[8],   // wo
        (float*)d_out);
}

// round 10
// speedup vs baseline: 1.7669x; 1.5380x over previous
#include <cuda_runtime.h>
#include <math.h>

// B=2048, T=64, IN=8, HID=6 qubits, OUT=8, NLAYERS=2, concat=16
#define NB    2048
#define NT    64
#define NIN   8
#define NHID  6
#define NOUT  8
#define NCAT  16
#define NLAY  2

// Precomputed x-part of the input linear: xpre[b][t][w] = b_in[w] + W_x[w]·x[b,t]
__device__ float g_xpre[NB * NT * NHID];

__device__ __forceinline__ float sigmoidf_(float v) {
    return 1.0f / (1.0f + __expf(-v));
}
__device__ __forceinline__ float tanhfast_(float v) {
    return 2.0f / (1.0f + __expf(-2.0f * v)) - 1.0f;
}

// Prepass: one thread per (b,t); computes the 6 x-dependent partial angles.
__global__ __launch_bounds__(256) void xpre_kernel(
    const float* __restrict__ x,      // [B, T, IN]
    const float* __restrict__ W_in,   // [HID, 16]  (cols 8..15 = x part)
    const float* __restrict__ b_in)   // [HID]
{
    int idx = blockIdx.x * blockDim.x + threadIdx.x;   // b*NT + t
    if (idx >= NB * NT) return;
    float4 xa = *reinterpret_cast<const float4*>(x + (size_t)idx * NIN);
    float4 xb = *reinterpret_cast<const float4*>(x + (size_t)idx * NIN + 4);
    #pragma unroll
    for (int w = 0; w < NHID; w++) {
        const float* wr = W_in + w * NCAT + 8;
        float acc = b_in[w];
        acc = fmaf(wr[0], xa.x, acc);
        acc = fmaf(wr[1], xa.y, acc);
        acc = fmaf(wr[2], xa.z, acc);
        acc = fmaf(wr[3], xa.w, acc);
        acc = fmaf(wr[4], xb.x, acc);
        acc = fmaf(wr[5], xb.y, acc);
        acc = fmaf(wr[6], xb.z, acc);
        acc = fmaf(wr[7], xb.w, acc);
        g_xpre[idx * NHID + w] = acc;
    }
}

// Layout: ONE warp = ONE batch element. The 4 octets (8-lane groups) evolve
// the same element's state through the 4 gate circuits (f,i,g,o = octet id).
// Wires 0,1,2 -> lane bits 2,1,0 (within octet); wires 3,4,5 -> in-thread
// amp bits 2,1,0. 8 complex amps per thread.
// Circuit folding:
//  - Embedding RX(y) + layer-1 RX(th1) merged: product state, angle y+th1.
//  - CNOT ring #1 folded into the product-state INDEX MAP (amp'(y)=amp(F^-1 y));
//    zero shuffles, per-thread constant selectors/phases.
//  - Final CNOT ring elided; permutation folded into expval signs.
__global__ __launch_bounds__(256) void qlstm_kernel(
    const float* __restrict__ W_in,   // [HID, 16] (cols 0..7 = h part)
    const float* __restrict__ W_out,  // [OUT, HID]
    const float* __restrict__ b_out,  // [OUT]
    const float* __restrict__ wf,     // [NLAY, HID]
    const float* __restrict__ wi,
    const float* __restrict__ wg,
    const float* __restrict__ wo,
    float* __restrict__ out)          // [B, T, OUT]
{
    __shared__ float2 sCS2[4][NHID];   // (cos, sin) of 0.5*layer-2 weight

    const int tid = threadIdx.x;
    if (tid < 4 * NHID) {
        const float* wp[4] = {wf, wi, wg, wo};
        int g = tid / NHID;
        int w = tid % NHID;
        float s_, c_;
        sincosf(0.5f * wp[g][NHID + w], &s_, &c_);    // layer index 1
        sCS2[g][w] = make_float2(c_, s_);
    }
    __syncthreads();

    const unsigned FULL = 0xffffffffu;
    const int lane = tid & 31;
    const int b    = blockIdx.x * (blockDim.x >> 5) + (tid >> 5);  // element
    const int oct  = lane >> 3;            // gate id (f,i,g,o)
    const int q    = lane & 7;             // wire0,1,2 = q bits 2,1,0
    const int oct6 = oct * 6;              // broadcast base for merged angles

    const int ibx0 = (q >> 2) & 1;   // wire0 bit
    const int ibx1 = (q >> 1) & 1;   // wire1 bit
    const int ibx2 = q & 1;          // wire2 bit
    const bool bx0 = ibx0, bx1 = ibx1, bx2 = ibx2;

    // ---- per-lane angle-row assignment: lanes 0..23 = (gate = lane/6, wire = lane%6)
    const int gl = lane / 6;               // gate for this lane's angle (lanes<24)
    const int wlane = lane - 6 * gl;       // wire for this lane's angle
    const bool aln = (lane < 24);

    // Hoisted weights
    float winh[8];                         // h-part row of W_in for wire wlane
    float th2;                             // 0.5 * layer-1 weight for (gl, wlane)
    {
        int row = aln ? wlane : 0;
        #pragma unroll
        for (int j = 0; j < 8; j++) winh[j] = W_in[row * NCAT + j];
        const float* wp[4] = {wf, wi, wg, wo};
        th2 = aln ? 0.5f * wp[gl][wlane] : 0.0f;     // layer index 0
    }
    float wrow[NHID];
    #pragma unroll
    for (int w = 0; w < NHID; w++) wrow[w] = W_out[q * NHID + w];
    const float bj = b_out[q];

    // ---- ring-1 folded phases: k(a) = popc(F^-1(y)) & 3, per-thread constants
    float sgnf[8];
    bool  evn[8];
    #pragma unroll
    for (int a = 0; a < 8; a++) {
        int a0 = a & 1, a1 = (a >> 1) & 1, a2 = (a >> 2) & 1;
        int z0 = ibx0 ^ a0;
        int z1 = ibx1 ^ ibx0 ^ a0;
        int z2 = ibx2 ^ ibx1;
        int z3 = a2 ^ ibx2;
        int z4 = a1 ^ a2;
        int z5 = a0 ^ a1;
        int k = (z0 + z1 + z2 + z3 + z4 + z5) & 3;
        sgnf[a] = (k == 0 || k == 3) ? 1.0f : -1.0f;
        evn[a]  = ((k & 1) == 0);
    }
    const bool x01 = (ibx1 ^ ibx0) != 0;   // z1 selector base
    const bool x12 = (ibx2 ^ ibx1) != 0;   // z2 selector (a-independent)

    // Per-wire layer-2 (cos,sin) for this octet's gate
    float2 cs2[NHID];
    #pragma unroll
    for (int w = 0; w < NHID; w++) cs2[w] = sCS2[oct][w];

    float* orow = out + (size_t)b * NT * NOUT;
    const float* prep = g_xpre + (size_t)b * NT * NHID;

    float h = 0.0f, c = 0.0f;
    float pre_cur = aln ? prep[wlane] : 0.0f;

    #pragma unroll 1
    for (int t = 0; t < NT; t++) {
        // ---- y = pre + W_h·h, merged half-angle = 0.5*y + 0.5*th1 ----
        float y = pre_cur;
        #pragma unroll
        for (int j = 0; j < 8; j++) {
            float hj = __shfl_sync(FULL, h, j);
            y = fmaf(winh[j], hj, y);
        }
        float pre_nxt = 0.0f;
        if (t + 1 < NT && aln) pre_nxt = prep[(t + 1) * NHID + wlane];

        float myS, myC;
        __sincosf(fmaf(0.5f, y, th2), &myS, &myC);
        // broadcast merged (cos,sin) per wire for this octet's gate
        float cw[NHID], sw[NHID];
        #pragma unroll
        for (int w = 0; w < NHID; w++) {
            cw[w] = __shfl_sync(FULL, myC, oct6 + w);
            sw[w] = __shfl_sync(FULL, myS, oct6 + w);
        }

        // ---- post-ring-1 state directly: amp'(y) = amp(F^-1 y) ----
        // factor(z_w) = z_w ? s_w : c_w ; z bits from per-thread constants
        float F0_0 = bx0 ? sw[0] : cw[0];
        float F0_1 = bx0 ? cw[0] : sw[0];
        float F1_0 = x01 ? sw[1] : cw[1];
        float F1_1 = x01 ? cw[1] : sw[1];
        float f2v  = x12 ? sw[2] : cw[2];
        float G0 = F0_0 * F1_0 * f2v;          // a0 = 0
        float G1 = F0_1 * F1_1 * f2v;          // a0 = 1
        float F3_0 = bx2 ? sw[3] : cw[3];      // a2 = 0
        float F3_1 = bx2 ? cw[3] : sw[3];      // a2 = 1

        float gr[8], gi[8];
        #pragma unroll
        for (int a = 0; a < 8; a++) {
            const int a0 = a & 1, a1 = (a >> 1) & 1, a2 = (a >> 2) & 1;
            float m = (a0 ? G1 : G0) * (a2 ? F3_1 : F3_0);
            m *= (a1 == a2) ? cw[4] : sw[4];
            m *= (a0 == a1) ? cw[5] : sw[5];
            float sm = sgnf[a] * m;
            gr[a] = evn[a] ? sm : 0.0f;
            gi[a] = evn[a] ? 0.0f : sm;
        }

        // ---- RX layer 2 ----
        #pragma unroll
        for (int w = 0; w < 3; w++) {          // lane wires (masks 4,2,1)
            const int m = 4 >> w;
            float2 cs = cs2[w];
            #pragma unroll
            for (int a = 0; a < 8; a++) {
                float pr = __shfl_xor_sync(FULL, gr[a], m);
                float pi = __shfl_xor_sync(FULL, gi[a], m);
                gr[a] = fmaf(cs.x, gr[a], cs.y * pi);
                gi[a] = fmaf(cs.x, gi[a], -cs.y * pr);
            }
        }
        #pragma unroll
        for (int w = 3; w < 6; w++) {          // in-thread wires (amp masks 4,2,1)
            const int m = 4 >> (w - 3);
            float2 cs = cs2[w];
            float nr[8], ni[8];
            #pragma unroll
            for (int a = 0; a < 8; a++) {
                nr[a] = fmaf(cs.x, gr[a], cs.y * gi[a ^ m]);
                ni[a] = fmaf(cs.x, gi[a], -cs.y * gr[a ^ m]);
            }
            #pragma unroll
            for (int a = 0; a < 8; a++) { gr[a] = nr[a]; gi[a] = ni[a]; }
        }
        // Final CNOT ring elided; folded into expval signs below.

        // ---- expvals (perm-folded signs) + output linear ----
        float acc;
        {
            float p[8];
            #pragma unroll
            for (int a = 0; a < 8; a++)
                p[a] = fmaf(gr[a], gr[a], gi[a] * gi[a]);
            float t01 = p[0] + p[1], t23 = p[2] + p[3];
            float t45 = p[4] + p[5], t67 = p[6] + p[7];
            float slo = t01 + t23, shi = t45 + t67;
            float uA  = slo + shi;
            float u3  = slo - shi;
            float u4  = (t01 + t67) - (t23 + t45);
            float u5  = ((p[0] + p[3]) + (p[5] + p[6]))
                      - ((p[1] + p[2]) + (p[4] + p[7]));

            // four interleaved butterfly chains
            float tA = __shfl_xor_sync(FULL, uA, 4);
            float t3 = __shfl_xor_sync(FULL, u3, 4);
            float t4 = __shfl_xor_sync(FULL, u4, 4);
            float t5 = __shfl_xor_sync(FULL, u5, 2);
            uA = bx0 ? tA - uA : uA - tA;
            u3 = bx0 ? t3 - u3 : u3 - t3;
            u4 = bx0 ? t4 - u4 : u4 - t4;
            u5 = bx1 ? t5 - u5 : u5 - t5;
            tA = __shfl_xor_sync(FULL, uA, 2);
            t3 = __shfl_xor_sync(FULL, u3, 2);
            t4 = __shfl_xor_sync(FULL, u4, 2);
            t5 = __shfl_xor_sync(FULL, u5, 1);
            uA = bx1 ? tA - uA : uA - tA;
            u3 = bx1 ? t3 - u3 : u3 - t3;
            u4 = bx1 ? t4 - u4 : u4 - t4;
            u5 = bx2 ? t5 - u5 : u5 - t5;
            tA = __shfl_xor_sync(FULL, uA, 1);
            t3 = __shfl_xor_sync(FULL, u3, 1);
            t4 = __shfl_xor_sync(FULL, u4, 1);
            t5 = __shfl_xor_sync(FULL, u5, 4);
            float E1 = uA + tA;
            float E2 = bx2 ? tA - uA : uA - tA;
            float E3 = bx2 ? t3 - u3 : u3 - t3;
            float E4 = bx2 ? t4 - u4 : u4 - t4;
            float E0 = u5 + t5;
            float E5 = bx0 ? t5 - u5 : u5 - t5;

            acc = bj;
            acc = fmaf(wrow[0], E0, acc);
            acc = fmaf(wrow[1], E1, acc);
            acc = fmaf(wrow[2], E2, acc);
            acc = fmaf(wrow[3], E3, acc);
            acc = fmaf(wrow[4], E4, acc);
            acc = fmaf(wrow[5], E5, acc);
        }

        // ---- gather all 4 gates for dim q ----
        float af = __shfl_sync(FULL, acc, q);        // octet 0 = f
        float ai = __shfl_sync(FULL, acc, 8 | q);    // octet 1 = i
        float ag = __shfl_sync(FULL, acc, 16 | q);   // octet 2 = g
        float ao = __shfl_sync(FULL, acc, 24 | q);   // octet 3 = o

        float fg = sigmoidf_(af);
        float ig = sigmoidf_(ai);
        float gg = tanhfast_(ag);
        float og = sigmoidf_(ao);
        c = fmaf(fg, c, ig * gg);
        h = og * tanhfast_(c);

        if (lane < NOUT) orow[t * NOUT + q] = h;
        pre_cur = pre_nxt;
    }
}

extern "C" void kernel_launch(void* const* d_in, const int* in_sizes, int n_in,
                              void* d_out, int out_size) {
    (void)in_sizes; (void)n_in; (void)out_size;
    xpre_kernel<<<(NB * NT + 255) / 256, 256>>>(
        (const float*)d_in[0],   // x
        (const float*)d_in[1],   // W_in
        (const float*)d_in[2]);  // b_in
    // 1 element/warp, 8 warps/block -> 256 blocks, 2048 warps
    qlstm_kernel<<<NB / 8, 256>>>(
        (const float*)d_in[1],   // W_in (h part)
        (const float*)d_in[3],   // W_out
        (const float*)d_in[4],   // b_out
        (const float*)d_in[5],   // wf
        (const float*)d_in[6],   // wi
        (const float*)d_in[7],   // wg
        (const float*)d_in[8],   // wo
        (float*)d_out);
}

// round 13
// speedup vs baseline: 1.9525x; 1.1051x over previous
#include <cuda_runtime.h>
#include <math.h>

// B=2048, T=64, IN=8, HID=6 qubits, OUT=8, NLAYERS=2, concat=16
#define NB    2048
#define NT    64
#define NIN   8
#define NHID  6
#define NOUT  8
#define NCAT  16
#define NLAY  2

// Precomputed x-part of the input linear: xpre[b][t][w] = b_in[w] + W_x[w]·x[b,t]
__device__ float g_xpre[NB * NT * NHID];

__device__ __forceinline__ float sigmoidf_(float v) {
    return 1.0f / (1.0f + __expf(-v));
}
__device__ __forceinline__ float tanhfast_(float v) {
    return 2.0f / (1.0f + __expf(-2.0f * v)) - 1.0f;
}

// ---- packed f32x2 helpers (sm_100+) ----
__device__ __forceinline__ unsigned long long pk2(float lo, float hi) {
    unsigned long long d;
    asm("mov.b64 %0, {%1, %2};" : "=l"(d) : "f"(lo), "f"(hi));
    return d;
}
__device__ __forceinline__ void upk2(unsigned long long v, float& lo, float& hi) {
    asm("mov.b64 {%0, %1}, %2;" : "=f"(lo), "=f"(hi) : "l"(v));
}
__device__ __forceinline__ unsigned long long fma2_(unsigned long long a,
                                                    unsigned long long b,
                                                    unsigned long long c) {
    unsigned long long d;
    asm("fma.rn.f32x2 %0, %1, %2, %3;" : "=l"(d) : "l"(a), "l"(b), "l"(c));
    return d;
}
__device__ __forceinline__ unsigned long long mul2_(unsigned long long a,
                                                    unsigned long long b) {
    unsigned long long d;
    asm("mul.rn.f32x2 %0, %1, %2;" : "=l"(d) : "l"(a), "l"(b));
    return d;
}

// Prepass: one thread per (b,t); computes the 6 x-dependent partial angles.
__global__ __launch_bounds__(256) void xpre_kernel(
    const float* __restrict__ x,      // [B, T, IN]
    const float* __restrict__ W_in,   // [HID, 16]  (cols 8..15 = x part)
    const float* __restrict__ b_in)   // [HID]
{
    int idx = blockIdx.x * blockDim.x + threadIdx.x;   // b*NT + t
    if (idx >= NB * NT) return;
    float4 xa = *reinterpret_cast<const float4*>(x + (size_t)idx * NIN);
    float4 xb = *reinterpret_cast<const float4*>(x + (size_t)idx * NIN + 4);
    #pragma unroll
    for (int w = 0; w < NHID; w++) {
        const float* wr = W_in + w * NCAT + 8;
        float acc = b_in[w];
        acc = fmaf(wr[0], xa.x, acc);
        acc = fmaf(wr[1], xa.y, acc);
        acc = fmaf(wr[2], xa.z, acc);
        acc = fmaf(wr[3], xa.w, acc);
        acc = fmaf(wr[4], xb.x, acc);
        acc = fmaf(wr[5], xb.y, acc);
        acc = fmaf(wr[6], xb.z, acc);
        acc = fmaf(wr[7], xb.w, acc);
        g_xpre[idx * NHID + w] = acc;
    }
}

// Layout: ONE warp = ONE batch element. 4 octets = 4 gate circuits (f,i,g,o).
// Wires 0,1,2 -> lane bits 2,1,0 (within octet); wires 3,4,5 -> in-thread
// amp bits 2,1,0. 8 complex amps per thread, packed 2-amps-per-b64 for RX2.
// Folds: embedding+layer1 RX merged product state; ring-1 via index map;
// final ring via expval signs (deferred + premultiplied into wrow).
__global__ __launch_bounds__(128, 4) void qlstm_kernel(
    const float* __restrict__ W_in,   // [HID, 16] (cols 0..7 = h part)
    const float* __restrict__ W_out,  // [OUT, HID]
    const float* __restrict__ b_out,  // [OUT]
    const float* __restrict__ wf,     // [NLAY, HID]
    const float* __restrict__ wi,
    const float* __restrict__ wg,
    const float* __restrict__ wo,
    float* __restrict__ out)          // [B, T, OUT]
{
    __shared__ float2 sCS2[4][NHID];   // (cos, sin) of 0.5*layer-2 weight

    const int tid = threadIdx.x;
    if (tid < 4 * NHID) {
        const float* wp[4] = {wf, wi, wg, wo};
        int g = tid / NHID;
        int w = tid % NHID;
        float s_, c_;
        sincosf(0.5f * wp[g][NHID + w], &s_, &c_);    // layer index 1
        sCS2[g][w] = make_float2(c_, s_);
    }
    __syncthreads();

    const unsigned FULL = 0xffffffffu;
    const int lane = tid & 31;
    const int b    = blockIdx.x * (blockDim.x >> 5) + (tid >> 5);  // element
    const int oct  = lane >> 3;            // gate id (f,i,g,o)
    const int q    = lane & 7;             // wire0,1,2 = q bits 2,1,0
    const int oct6 = oct * 6;              // broadcast base for merged angles

    const int ibx0 = (q >> 2) & 1;   // wire0 bit
    const int ibx1 = (q >> 1) & 1;   // wire1 bit
    const int ibx2 = q & 1;          // wire2 bit
    const bool bx0 = ibx0, bx2 = ibx2;

    // per-lane angle-row: lanes 0..23 = (gate = lane/6, wire = lane%6)
    const int gl = lane / 6;
    const int wlane = lane - 6 * gl;
    const bool aln = (lane < 24);

    // Hoisted weights
    float winh[8];
    float th2;
    {
        int row = aln ? wlane : 0;
        #pragma unroll
        for (int j = 0; j < 8; j++) winh[j] = W_in[row * NCAT + j];
        const float* wp[4] = {wf, wi, wg, wo};
        th2 = aln ? 0.5f * wp[gl][wlane] : 0.0f;     // layer index 0
    }
    // W_out row with deferred-butterfly signs premultiplied:
    //   wrow[0] *= s12, wrow[1] *= s01, wrow[2..5] *= s012
    float wrow[NHID];
    {
        float s01  = ((ibx0 + ibx1) & 1) ? -1.0f : 1.0f;
        float s12  = ((ibx1 + ibx2) & 1) ? -1.0f : 1.0f;
        float s012 = ((ibx0 + ibx1 + ibx2) & 1) ? -1.0f : 1.0f;
        wrow[0] = W_out[q * NHID + 0] * s12;
        wrow[1] = W_out[q * NHID + 1] * s01;
        wrow[2] = W_out[q * NHID + 2] * s012;
        wrow[3] = W_out[q * NHID + 3] * s012;
        wrow[4] = W_out[q * NHID + 4] * s012;
        wrow[5] = W_out[q * NHID + 5] * s012;
    }
    const float bj = b_out[q];

    // ring-1 folded phases: k(a) = popc(F^-1(y)) & 3, per-thread constants
    float sgnf[8];
    bool  evn[8];
    #pragma unroll
    for (int a = 0; a < 8; a++) {
        int a0 = a & 1, a1 = (a >> 1) & 1, a2 = (a >> 2) & 1;
        int z0 = ibx0 ^ a0;
        int z1 = ibx1 ^ ibx0 ^ a0;
        int z2 = ibx2 ^ ibx1;
        int z3 = a2 ^ ibx2;
        int z4 = a1 ^ a2;
        int z5 = a0 ^ a1;
        int k = (z0 + z1 + z2 + z3 + z4 + z5) & 3;
        sgnf[a] = (k == 0 || k == 3) ? 1.0f : -1.0f;
        evn[a]  = ((k & 1) == 0);
    }
    const bool x01 = (ibx1 ^ ibx0) != 0;
    const bool x12 = (ibx2 ^ ibx1) != 0;

    // Layer-2 packed (c,c)/(s,s)/(-s,-s) for wires 0..4; wire 5 scalar
    unsigned long long cc2[5], ss2[5], sn2[5];
    float c5, s5;
    {
        #pragma unroll
        for (int w = 0; w < 5; w++) {
            float2 cs = sCS2[oct][w];
            cc2[w] = pk2(cs.x, cs.x);
            ss2[w] = pk2(cs.y, cs.y);
            sn2[w] = pk2(-cs.y, -cs.y);
        }
        float2 cs = sCS2[oct][5];
        c5 = cs.x; s5 = cs.y;
    }

    float* orow = out + (size_t)b * NT * NOUT;
    const float* prep = g_xpre + (size_t)b * NT * NHID;

    float h = 0.0f, c = 0.0f;
    float pre_cur = aln ? prep[wlane] : 0.0f;

    #pragma unroll 1
    for (int t = 0; t < NT; t++) {
        // ---- y = pre + W_h·h, merged half-angle = 0.5*y + th2 ----
        float y = pre_cur;
        #pragma unroll
        for (int j = 0; j < 8; j++) {
            float hj = __shfl_sync(FULL, h, j);
            y = fmaf(winh[j], hj, y);
        }
        float pre_nxt = 0.0f;
        if (t + 1 < NT && aln) pre_nxt = prep[(t + 1) * NHID + wlane];

        float myS, myC;
        __sincosf(fmaf(0.5f, y, th2), &myS, &myC);
        float cw[NHID], sw[NHID];
        #pragma unroll
        for (int w = 0; w < NHID; w++) {
            cw[w] = __shfl_sync(FULL, myC, oct6 + w);
            sw[w] = __shfl_sync(FULL, myS, oct6 + w);
        }

        // ---- post-ring-1 state directly: amp'(y) = amp(F^-1 y) ----
        float F0_0 = bx0 ? sw[0] : cw[0];
        float F0_1 = bx0 ? cw[0] : sw[0];
        float F1_0 = x01 ? sw[1] : cw[1];
        float F1_1 = x01 ? cw[1] : sw[1];
        float f2v  = x12 ? sw[2] : cw[2];
        float G0 = F0_0 * F1_0 * f2v;          // a0 = 0
        float G1 = F0_1 * F1_1 * f2v;          // a0 = 1
        float F3_0 = bx2 ? sw[3] : cw[3];      // a2 = 0
        float F3_1 = bx2 ? cw[3] : sw[3];      // a2 = 1

        float gr[8], gi[8];
        #pragma unroll
        for (int a = 0; a < 8; a++) {
            const int a0 = a & 1, a1 = (a >> 1) & 1, a2 = (a >> 2) & 1;
            float m = (a0 ? G1 : G0) * (a2 ? F3_1 : F3_0);
            m *= (a1 == a2) ? cw[4] : sw[4];
            m *= (a0 == a1) ? cw[5] : sw[5];
            float sm = sgnf[a] * m;
            gr[a] = evn[a] ? sm : 0.0f;
            gi[a] = evn[a] ? 0.0f : sm;
        }

        // ---- pack amp pairs: pack p = amps (2p, 2p+1) ----
        unsigned long long R[4], I[4];
        #pragma unroll
        for (int p = 0; p < 4; p++) {
            R[p] = pk2(gr[2 * p], gr[2 * p + 1]);
            I[p] = pk2(gi[2 * p], gi[2 * p + 1]);
        }

        // ---- RX layer 2, lane wires 0..2 (shfl masks 4,2,1), packed ----
        #pragma unroll
        for (int w = 0; w < 3; w++) {
            const int m = 4 >> w;
            unsigned long long Rp[4], Ip[4];
            #pragma unroll
            for (int p = 0; p < 4; p++) {
                Rp[p] = __shfl_xor_sync(FULL, R[p], m);
                Ip[p] = __shfl_xor_sync(FULL, I[p], m);
            }
            #pragma unroll
            for (int p = 0; p < 4; p++) {
                R[p] = fma2_(cc2[w], R[p], mul2_(ss2[w], Ip[p]));
                I[p] = fma2_(cc2[w], I[p], mul2_(sn2[w], Rp[p]));
            }
        }
        // ---- wires 3,4 (amp masks 4,2 -> pack partners ^2, ^1), packed ----
        #pragma unroll
        for (int w = 3; w < 5; w++) {
            const int pm = (w == 3) ? 2 : 1;
            unsigned long long nR[4], nI[4];
            #pragma unroll
            for (int p = 0; p < 4; p++) {
                nR[p] = fma2_(cc2[w], R[p], mul2_(ss2[w], I[p ^ pm]));
                nI[p] = fma2_(cc2[w], I[p], mul2_(sn2[w], R[p ^ pm]));
            }
            #pragma unroll
            for (int p = 0; p < 4; p++) { R[p] = nR[p]; I[p] = nI[p]; }
        }
        // ---- wire 5 (amp mask 1, intra-pack): scalar ----
        #pragma unroll
        for (int p = 0; p < 4; p++) {
            upk2(R[p], gr[2 * p], gr[2 * p + 1]);
            upk2(I[p], gi[2 * p], gi[2 * p + 1]);
        }
        float hr[8], hi2[8];
        #pragma unroll
        for (int a = 0; a < 8; a++) {
            hr[a]  = fmaf(c5, gr[a], s5 * gi[a ^ 1]);
            hi2[a] = fmaf(c5, gi[a], -s5 * gr[a ^ 1]);
        }

        // ---- expvals: deferred-sign butterflies (signs in wrow) ----
        float acc;
        {
            float p[8];
            #pragma unroll
            for (int a = 0; a < 8; a++)
                p[a] = fmaf(hr[a], hr[a], hi2[a] * hi2[a]);
            float t01 = p[0] + p[1], t23 = p[2] + p[3];
            float t45 = p[4] + p[5], t67 = p[6] + p[7];
            float slo = t01 + t23, shi = t45 + t67;
            float uA  = slo + shi;
            float u3  = slo - shi;
            float u4  = (t01 + t67) - (t23 + t45);
            float u5  = ((p[0] + p[3]) + (p[5] + p[6]))
                      - ((p[1] + p[2]) + (p[4] + p[7]));

            // stage 1 (A,A3,A4: mask4; A5: mask2)
            float tA = __shfl_xor_sync(FULL, uA, 4);
            float t3 = __shfl_xor_sync(FULL, u3, 4);
            float t4 = __shfl_xor_sync(FULL, u4, 4);
            float t5 = __shfl_xor_sync(FULL, u5, 2);
            uA -= tA; u3 -= t3; u4 -= t4; u5 -= t5;
            // stage 2 (A,A3,A4: mask2; A5: mask1)
            tA = __shfl_xor_sync(FULL, uA, 2);
            t3 = __shfl_xor_sync(FULL, u3, 2);
            t4 = __shfl_xor_sync(FULL, u4, 2);
            t5 = __shfl_xor_sync(FULL, u5, 1);
            uA -= tA; u3 -= t3; u4 -= t4; u5 -= t5;
            // stage 3 (A,A3,A4: mask1; A5: mask4)
            tA = __shfl_xor_sync(FULL, uA, 1);
            t3 = __shfl_xor_sync(FULL, u3, 1);
            t4 = __shfl_xor_sync(FULL, u4, 1);
            t5 = __shfl_xor_sync(FULL, u5, 4);
            float E1 = uA + tA;       // * s01   (in wrow[1])
            float E2 = uA - tA;       // * s012  (in wrow[2])
            float E3 = u3 - t3;       // * s012
            float E4 = u4 - t4;       // * s012
            float E0 = u5 + t5;       // * s12   (in wrow[0])
            float E5 = u5 - t5;       // * s012

            acc = bj;
            acc = fmaf(wrow[0], E0, acc);
            acc = fmaf(wrow[1], E1, acc);
            acc = fmaf(wrow[2], E2, acc);
            acc = fmaf(wrow[3], E3, acc);
            acc = fmaf(wrow[4], E4, acc);
            acc = fmaf(wrow[5], E5, acc);
        }

        // ---- gather all 4 gates for dim q ----
        float af = __shfl_sync(FULL, acc, q);        // octet 0 = f
        float ai = __shfl_sync(FULL, acc, 8 | q);    // octet 1 = i
        float ag = __shfl_sync(FULL, acc, 16 | q);   // octet 2 = g
        float ao = __shfl_sync(FULL, acc, 24 | q);   // octet 3 = o

        float fg = sigmoidf_(af);
        float ig = sigmoidf_(ai);
        float gg = tanhfast_(ag);
        float og = sigmoidf_(ao);
        c = fmaf(fg, c, ig * gg);
        h = og * tanhfast_(c);

        if (lane < NOUT) orow[t * NOUT + q] = h;
        pre_cur = pre_nxt;
    }
}

extern "C" void kernel_launch(void* const* d_in, const int* in_sizes, int n_in,
                              void* d_out, int out_size) {
    (void)in_sizes; (void)n_in; (void)out_size;
    xpre_kernel<<<(NB * NT + 255) / 256, 256>>>(
        (const float*)d_in[0],   // x
        (const float*)d_in[1],   // W_in
        (const float*)d_in[2]);  // b_in
    // 1 element/warp, 4 warps/block -> 512 blocks, 2048 warps
    qlstm_kernel<<<NB / 4, 128>>>(
        (const float*)d_in[1],   // W_in (h part)
        (const float*)d_in[3],   // W_out
        (const float*)d_in[4],   // b_out
        (const float*)d_in[5],   // wf
        (const float*)d_in[6],   // wi
        (const float*)d_in[7],   // wg
        (const float*)d_in[8],   // wo
        (float*)d_out);
}

// round 15
// speedup vs baseline: 2.0923x; 1.0716x over previous
#include <cuda_runtime.h>
#include <math.h>

// B=2048, T=64, IN=8, HID=6 qubits, OUT=8, NLAYERS=2, concat=16
#define NB    2048
#define NT    64
#define NIN   8
#define NHID  6
#define NOUT  8
#define NCAT  16
#define NLAY  2

// Precomputed x-part of the input linear: xpre[b][t][w] = b_in[w] + W_x[w]·x[b,t]
__device__ float g_xpre[NB * NT * NHID];

__device__ __forceinline__ float sigmoidf_(float v) {
    return 1.0f / (1.0f + __expf(-v));
}
__device__ __forceinline__ float tanhfast_(float v) {
    return 2.0f / (1.0f + __expf(-2.0f * v)) - 1.0f;
}

// ---- packed f32x2 helpers (sm_100+) ----
__device__ __forceinline__ unsigned long long pk2(float lo, float hi) {
    unsigned long long d;
    asm("mov.b64 %0, {%1, %2};" : "=l"(d) : "f"(lo), "f"(hi));
    return d;
}
__device__ __forceinline__ void upk2(unsigned long long v, float& lo, float& hi) {
    asm("mov.b64 {%0, %1}, %2;" : "=f"(lo), "=f"(hi) : "l"(v));
}
__device__ __forceinline__ unsigned long long fma2_(unsigned long long a,
                                                    unsigned long long b,
                                                    unsigned long long c) {
    unsigned long long d;
    asm("fma.rn.f32x2 %0, %1, %2, %3;" : "=l"(d) : "l"(a), "l"(b), "l"(c));
    return d;
}
__device__ __forceinline__ unsigned long long mul2_(unsigned long long a,
                                                    unsigned long long b) {
    unsigned long long d;
    asm("mul.rn.f32x2 %0, %1, %2;" : "=l"(d) : "l"(a), "l"(b));
    return d;
}

// Prepass: one thread per (b,t); computes the 6 x-dependent partial angles.
__global__ __launch_bounds__(256) void xpre_kernel(
    const float* __restrict__ x,      // [B, T, IN]
    const float* __restrict__ W_in,   // [HID, 16]  (cols 8..15 = x part)
    const float* __restrict__ b_in)   // [HID]
{
    int idx = blockIdx.x * blockDim.x + threadIdx.x;   // b*NT + t
    if (idx >= NB * NT) return;
    float4 xa = *reinterpret_cast<const float4*>(x + (size_t)idx * NIN);
    float4 xb = *reinterpret_cast<const float4*>(x + (size_t)idx * NIN + 4);
    #pragma unroll
    for (int w = 0; w < NHID; w++) {
        const float* wr = W_in + w * NCAT + 8;
        float acc = b_in[w];
        acc = fmaf(wr[0], xa.x, acc);
        acc = fmaf(wr[1], xa.y, acc);
        acc = fmaf(wr[2], xa.z, acc);
        acc = fmaf(wr[3], xa.w, acc);
        acc = fmaf(wr[4], xb.x, acc);
        acc = fmaf(wr[5], xb.y, acc);
        acc = fmaf(wr[6], xb.z, acc);
        acc = fmaf(wr[7], xb.w, acc);
        g_xpre[idx * NHID + w] = acc;
    }
}

// Layout: ONE warp = ONE batch element. 4 octets = 4 gate circuits (f,i,g,o).
// Wires 0,1,2 -> lane bits 2,1,0 (within octet); wires 3,4,5 -> in-thread
// amp bits 2,1,0. 8 complex amps per thread.
// Folds: embedding+layer1 RX merged product state; ring-1 via index map
// (parity(popc(F^-1 y)) == a0, so even amps are REAL and odd amps IMAGINARY
// -> state entering RX2 is represented as 8 reals; the wire-0 RX stage is
// computed sparsely with half the shuffle volume); final ring via expval
// signs (deferred + premultiplied into wrow).
__global__ __launch_bounds__(128, 4) void qlstm_kernel(
    const float* __restrict__ W_in,   // [HID, 16] (cols 0..7 = h part)
    const float* __restrict__ W_out,  // [OUT, HID]
    const float* __restrict__ b_out,  // [OUT]
    const float* __restrict__ wf,     // [NLAY, HID]
    const float* __restrict__ wi,
    const float* __restrict__ wg,
    const float* __restrict__ wo,
    float* __restrict__ out)          // [B, T, OUT]
{
    __shared__ float2 sCS2[4][NHID];   // (cos, sin) of 0.5*layer-2 weight

    const int tid = threadIdx.x;
    if (tid < 4 * NHID) {
        const float* wp[4] = {wf, wi, wg, wo};
        int g = tid / NHID;
        int w = tid % NHID;
        float s_, c_;
        sincosf(0.5f * wp[g][NHID + w], &s_, &c_);    // layer index 1
        sCS2[g][w] = make_float2(c_, s_);
    }
    __syncthreads();

    const unsigned FULL = 0xffffffffu;
    const int lane = tid & 31;
    const int b    = blockIdx.x * (blockDim.x >> 5) + (tid >> 5);  // element
    const int oct  = lane >> 3;            // gate id (f,i,g,o)
    const int q    = lane & 7;             // wire0,1,2 = q bits 2,1,0
    const int oct6 = oct * 6;              // broadcast base for merged angles

    const int ibx0 = (q >> 2) & 1;   // wire0 bit
    const int ibx1 = (q >> 1) & 1;   // wire1 bit
    const int ibx2 = q & 1;          // wire2 bit
    const bool bx0 = ibx0, bx2 = ibx2;

    // per-lane angle-row: lanes 0..23 = (gate = lane/6, wire = lane%6)
    const int gl = lane / 6;
    const int wlane = lane - 6 * gl;
    const bool aln = (lane < 24);

    // Hoisted weights
    float winh[8];
    float th2;
    {
        int row = aln ? wlane : 0;
        #pragma unroll
        for (int j = 0; j < 8; j++) winh[j] = W_in[row * NCAT + j];
        const float* wp[4] = {wf, wi, wg, wo};
        th2 = aln ? 0.5f * wp[gl][wlane] : 0.0f;     // layer index 0
    }
    // W_out row with deferred-butterfly signs premultiplied:
    //   wrow[0] *= s12, wrow[1] *= s01, wrow[2..5] *= s012
    float wrow[NHID];
    {
        float s01  = ((ibx0 + ibx1) & 1) ? -1.0f : 1.0f;
        float s12  = ((ibx1 + ibx2) & 1) ? -1.0f : 1.0f;
        float s012 = ((ibx0 + ibx1 + ibx2) & 1) ? -1.0f : 1.0f;
        wrow[0] = W_out[q * NHID + 0] * s12;
        wrow[1] = W_out[q * NHID + 1] * s01;
        wrow[2] = W_out[q * NHID + 2] * s012;
        wrow[3] = W_out[q * NHID + 3] * s012;
        wrow[4] = W_out[q * NHID + 4] * s012;
        wrow[5] = W_out[q * NHID + 5] * s012;
    }
    const float bj = b_out[q];

    // ring-1 folded phases: k(a) = popc(F^-1(y)) & 3. parity(k) == a0 always,
    // so only the sign (+1 for k in {0,3}, -1 for {1,2}) is needed:
    //   even a: gr = sgnf*m, gi = 0;  odd a: gi = sgnf*m, gr = 0.
    float sgnf[8];
    #pragma unroll
    for (int a = 0; a < 8; a++) {
        int a0 = a & 1, a1 = (a >> 1) & 1, a2 = (a >> 2) & 1;
        int z0 = ibx0 ^ a0;
        int z1 = ibx1 ^ ibx0 ^ a0;
        int z2 = ibx2 ^ ibx1;
        int z3 = a2 ^ ibx2;
        int z4 = a1 ^ a2;
        int z5 = a0 ^ a1;
        int k = (z0 + z1 + z2 + z3 + z4 + z5) & 3;
        sgnf[a] = (k == 0 || k == 3) ? 1.0f : -1.0f;
    }
    const bool x01 = (ibx1 ^ ibx0) != 0;
    const bool x12 = (ibx2 ^ ibx1) != 0;

    // Layer-2 constants: wire0 & wire5 scalar; wires 1..4 packed
    unsigned long long cc2[5], ss2[5], sn2[5];
    float c0, s0, c5, s5;
    {
        #pragma unroll
        for (int w = 1; w < 5; w++) {
            float2 cs = sCS2[oct][w];
            cc2[w] = pk2(cs.x, cs.x);
            ss2[w] = pk2(cs.y, cs.y);
            sn2[w] = pk2(-cs.y, -cs.y);
        }
        float2 csw0 = sCS2[oct][0];
        c0 = csw0.x; s0 = csw0.y;
        float2 csw5 = sCS2[oct][5];
        c5 = csw5.x; s5 = csw5.y;
    }

    float* orow = out + (size_t)b * NT * NOUT;
    const float* prep = g_xpre + (size_t)b * NT * NHID;

    float h = 0.0f, c = 0.0f;
    float pre_cur = aln ? prep[wlane] : 0.0f;

    #pragma unroll 1
    for (int t = 0; t < NT; t++) {
        // ---- y = pre + W_h·h, merged half-angle = 0.5*y + th2 ----
        float y = pre_cur;
        #pragma unroll
        for (int j = 0; j < 8; j++) {
            float hj = __shfl_sync(FULL, h, j);
            y = fmaf(winh[j], hj, y);
        }
        float pre_nxt = 0.0f;
        if (t + 1 < NT && aln) pre_nxt = prep[(t + 1) * NHID + wlane];

        float myS, myC;
        __sincosf(fmaf(0.5f, y, th2), &myS, &myC);
        float cw[NHID], sw[NHID];
        #pragma unroll
        for (int w = 0; w < NHID; w++) {
            cw[w] = __shfl_sync(FULL, myC, oct6 + w);
            sw[w] = __shfl_sync(FULL, myS, oct6 + w);
        }

        // ---- post-ring-1 state (real-valued v; placement by a-parity) ----
        float F0_0 = bx0 ? sw[0] : cw[0];
        float F0_1 = bx0 ? cw[0] : sw[0];
        float F1_0 = x01 ? sw[1] : cw[1];
        float F1_1 = x01 ? cw[1] : sw[1];
        float f2v  = x12 ? sw[2] : cw[2];
        float G0 = F0_0 * F1_0 * f2v;          // a0 = 0
        float G1 = F0_1 * F1_1 * f2v;          // a0 = 1
        float F3_0 = bx2 ? sw[3] : cw[3];      // a2 = 0
        float F3_1 = bx2 ? cw[3] : sw[3];      // a2 = 1
        // wires 4,5 product table (indexed by compile-time z4=a1^a2, z5=a0^a1)
        const float M00 = cw[4] * cw[5];
        const float M01 = cw[4] * sw[5];
        const float M10 = sw[4] * cw[5];
        const float M11 = sw[4] * sw[5];

        float v[8];
        #pragma unroll
        for (int a = 0; a < 8; a++) {
            const int a0 = a & 1, a1 = (a >> 1) & 1, a2 = (a >> 2) & 1;
            const int z4 = a1 ^ a2, z5 = a0 ^ a1;
            float m = (a0 ? G1 : G0) * (a2 ? F3_1 : F3_0);
            m *= z4 ? (z5 ? M11 : M10) : (z5 ? M01 : M00);
            v[a] = m * sgnf[a];
        }

        // ---- RX2 wire 0 (lane mask 4): sparse stage, half shuffle volume ----
        unsigned long long V[4];
        #pragma unroll
        for (int p = 0; p < 4; p++) V[p] = pk2(v[2 * p], v[2 * p + 1]);
        float vp[8];
        #pragma unroll
        for (int p = 0; p < 4; p++) {
            unsigned long long Vx = __shfl_xor_sync(FULL, V[p], 4);
            upk2(Vx, vp[2 * p], vp[2 * p + 1]);
        }
        float gr[8], gi[8];
        #pragma unroll
        for (int p = 0; p < 4; p++) {
            gr[2 * p]     = c0 * v[2 * p];        // even: real in, real out
            gi[2 * p]     = -s0 * vp[2 * p];
            gr[2 * p + 1] = s0 * vp[2 * p + 1];   // odd: imag in
            gi[2 * p + 1] = c0 * v[2 * p + 1];
        }

        // ---- pack amp pairs for the dense stages ----
        unsigned long long R[4], I[4];
        #pragma unroll
        for (int p = 0; p < 4; p++) {
            R[p] = pk2(gr[2 * p], gr[2 * p + 1]);
            I[p] = pk2(gi[2 * p], gi[2 * p + 1]);
        }

        // ---- RX2 wires 1,2 (lane masks 2,1), packed ----
        #pragma unroll
        for (int w = 1; w < 3; w++) {
            const int m = 4 >> w;
            unsigned long long Rp[4], Ip[4];
            #pragma unroll
            for (int p = 0; p < 4; p++) {
                Rp[p] = __shfl_xor_sync(FULL, R[p], m);
                Ip[p] = __shfl_xor_sync(FULL, I[p], m);
            }
            #pragma unroll
            for (int p = 0; p < 4; p++) {
                R[p] = fma2_(cc2[w], R[p], mul2_(ss2[w], Ip[p]));
                I[p] = fma2_(cc2[w], I[p], mul2_(sn2[w], Rp[p]));
            }
        }
        // ---- wires 3,4 (amp masks 4,2 -> pack partners ^2, ^1), packed ----
        #pragma unroll
        for (int w = 3; w < 5; w++) {
            const int pm = (w == 3) ? 2 : 1;
            unsigned long long nR[4], nI[4];
            #pragma unroll
            for (int p = 0; p < 4; p++) {
                nR[p] = fma2_(cc2[w], R[p], mul2_(ss2[w], I[p ^ pm]));
                nI[p] = fma2_(cc2[w], I[p], mul2_(sn2[w], R[p ^ pm]));
            }
            #pragma unroll
            for (int p = 0; p < 4; p++) { R[p] = nR[p]; I[p] = nI[p]; }
        }
        // ---- wire 5 (amp mask 1, intra-pack): scalar ----
        #pragma unroll
        for (int p = 0; p < 4; p++) {
            upk2(R[p], gr[2 * p], gr[2 * p + 1]);
            upk2(I[p], gi[2 * p], gi[2 * p + 1]);
        }
        float hr[8], hi2[8];
        #pragma unroll
        for (int a = 0; a < 8; a++) {
            hr[a]  = fmaf(c5, gr[a], s5 * gi[a ^ 1]);
            hi2[a] = fmaf(c5, gi[a], -s5 * gr[a ^ 1]);
        }

        // ---- expvals: deferred-sign butterflies (signs in wrow) ----
        float acc;
        {
            float p[8];
            #pragma unroll
            for (int a = 0; a < 8; a++)
                p[a] = fmaf(hr[a], hr[a], hi2[a] * hi2[a]);
            float t01 = p[0] + p[1], t23 = p[2] + p[3];
            float t45 = p[4] + p[5], t67 = p[6] + p[7];
            float slo = t01 + t23, shi = t45 + t67;
            float uA  = slo + shi;
            float u3  = slo - shi;
            float u4  = (t01 + t67) - (t23 + t45);
            float u5  = ((p[0] + p[3]) + (p[5] + p[6]))
                      - ((p[1] + p[2]) + (p[4] + p[7]));

            // stage 1 (A,A3,A4: mask4; A5: mask2)
            float tA = __shfl_xor_sync(FULL, uA, 4);
            float t3 = __shfl_xor_sync(FULL, u3, 4);
            float t4 = __shfl_xor_sync(FULL, u4, 4);
            float t5 = __shfl_xor_sync(FULL, u5, 2);
            uA -= tA; u3 -= t3; u4 -= t4; u5 -= t5;
            // stage 2 (A,A3,A4: mask2; A5: mask1)
            tA = __shfl_xor_sync(FULL, uA, 2);
            t3 = __shfl_xor_sync(FULL, u3, 2);
            t4 = __shfl_xor_sync(FULL, u4, 2);
            t5 = __shfl_xor_sync(FULL, u5, 1);
            uA -= tA; u3 -= t3; u4 -= t4; u5 -= t5;
            // stage 3 (A,A3,A4: mask1; A5: mask4)
            tA = __shfl_xor_sync(FULL, uA, 1);
            t3 = __shfl_xor_sync(FULL, u3, 1);
            t4 = __shfl_xor_sync(FULL, u4, 1);
            t5 = __shfl_xor_sync(FULL, u5, 4);
            float E1 = uA + tA;       // * s01   (in wrow[1])
            float E2 = uA - tA;       // * s012  (in wrow[2])
            float E3 = u3 - t3;       // * s012
            float E4 = u4 - t4;       // * s012
            float E0 = u5 + t5;       // * s12   (in wrow[0])
            float E5 = u5 - t5;       // * s012

            acc = bj;
            acc = fmaf(wrow[0], E0, acc);
            acc = fmaf(wrow[1], E1, acc);
            acc = fmaf(wrow[2], E2, acc);
            acc = fmaf(wrow[3], E3, acc);
            acc = fmaf(wrow[4], E4, acc);
            acc = fmaf(wrow[5], E5, acc);
        }

        // ---- gather all 4 gates for dim q ----
        float af = __shfl_sync(FULL, acc, q);        // octet 0 = f
        float ai = __shfl_sync(FULL, acc, 8 | q);    // octet 1 = i
        float ag = __shfl_sync(FULL, acc, 16 | q);   // octet 2 = g
        float ao = __shfl_sync(FULL, acc, 24 | q);   // octet 3 = o

        float fg = sigmoidf_(af);
        float ig = sigmoidf_(ai);
        float gg = tanhfast_(ag);
        float og = sigmoidf_(ao);
        c = fmaf(fg, c, ig * gg);
        h = og * tanhfast_(c);

        if (lane < NOUT) orow[t * NOUT + q] = h;
        pre_cur = pre_nxt;
    }
}

extern "C" void kernel_launch(void* const* d_in, const int* in_sizes, int n_in,
                              void* d_out, int out_size) {
    (void)in_sizes; (void)n_in; (void)out_size;
    xpre_kernel<<<(NB * NT + 255) / 256, 256>>>(
        (const float*)d_in[0],   // x
        (const float*)d_in[1],   // W_in
        (const float*)d_in[2]);  // b_in
    // 1 element/warp, 4 warps/block -> 512 blocks, 2048 warps
    qlstm_kernel<<<NB / 4, 128>>>(
        (const float*)d_in[1],   // W_in (h part)
        (const float*)d_in[3],   // W_out
        (const float*)d_in[4],   // b_out
        (const float*)d_in[5],   // wf
        (const float*)d_in[6],   // wi
        (const float*)d_in[7],   // wg
        (const float*)d_in[8],   // wo
        (float*)d_out);
}

// round 16
// speedup vs baseline: 2.1223x; 1.0144x over previous
#include <cuda_runtime.h>
#include <math.h>

// B=2048, T=64, IN=8, HID=6 qubits, OUT=8, NLAYERS=2, concat=16
#define NB    2048
#define NT    64
#define NIN   8
#define NHID  6
#define NOUT  8
#define NCAT  16
#define NLAY  2

// Precomputed x-part of the input linear: xpre[b][t][w] = b_in[w] + W_x[w]·x[b,t]
__device__ float g_xpre[NB * NT * NHID];

__device__ __forceinline__ float sigmoidf_(float v) {
    return 1.0f / (1.0f + __expf(-v));
}
__device__ __forceinline__ float tanhfast_(float v) {
    return 2.0f / (1.0f + __expf(-2.0f * v)) - 1.0f;
}

// ---- packed f32x2 helpers (sm_100+) ----
__device__ __forceinline__ unsigned long long pk2(float lo, float hi) {
    unsigned long long d;
    asm("mov.b64 %0, {%1, %2};" : "=l"(d) : "f"(lo), "f"(hi));
    return d;
}
__device__ __forceinline__ void upk2(unsigned long long v, float& lo, float& hi) {
    asm("mov.b64 {%0, %1}, %2;" : "=f"(lo), "=f"(hi) : "l"(v));
}
__device__ __forceinline__ unsigned long long fma2_(unsigned long long a,
                                                    unsigned long long b,
                                                    unsigned long long c) {
    unsigned long long d;
    asm("fma.rn.f32x2 %0, %1, %2, %3;" : "=l"(d) : "l"(a), "l"(b), "l"(c));
    return d;
}
__device__ __forceinline__ unsigned long long mul2_(unsigned long long a,
                                                    unsigned long long b) {
    unsigned long long d;
    asm("mul.rn.f32x2 %0, %1, %2;" : "=l"(d) : "l"(a), "l"(b));
    return d;
}

// Prepass: one thread per (b,t); computes the 6 x-dependent partial angles.
__global__ __launch_bounds__(256) void xpre_kernel(
    const float* __restrict__ x,      // [B, T, IN]
    const float* __restrict__ W_in,   // [HID, 16]  (cols 8..15 = x part)
    const float* __restrict__ b_in)   // [HID]
{
    int idx = blockIdx.x * blockDim.x + threadIdx.x;   // b*NT + t
    if (idx >= NB * NT) return;
    float4 xa = *reinterpret_cast<const float4*>(x + (size_t)idx * NIN);
    float4 xb = *reinterpret_cast<const float4*>(x + (size_t)idx * NIN + 4);
    #pragma unroll
    for (int w = 0; w < NHID; w++) {
        const float* wr = W_in + w * NCAT + 8;
        float acc = b_in[w];
        acc = fmaf(wr[0], xa.x, acc);
        acc = fmaf(wr[1], xa.y, acc);
        acc = fmaf(wr[2], xa.z, acc);
        acc = fmaf(wr[3], xa.w, acc);
        acc = fmaf(wr[4], xb.x, acc);
        acc = fmaf(wr[5], xb.y, acc);
        acc = fmaf(wr[6], xb.z, acc);
        acc = fmaf(wr[7], xb.w, acc);
        g_xpre[idx * NHID + w] = acc;
    }
}

// Layout: ONE warp = ONE batch element. 4 octets = 4 gate circuits (f,i,g,o).
// Wires 0,1,2 -> lane bits 2,1,0 (within octet); wires 3,4,5 -> in-thread
// amp bits 2,1,0. 8 complex amps per thread.
// Folds: embedding+layer1 RX merged product state (fully f32x2-packed
// construct); ring-1 via index map (even amps real / odd imaginary ->
// sparse packed wire-0 stage); wire-5 rotation folded into the probability
// computation (p from n=|amp|^2 and cross term w); final ring via expval
// signs (deferred + premultiplied into wrow).
__global__ __launch_bounds__(128, 4) void qlstm_kernel(
    const float* __restrict__ W_in,   // [HID, 16] (cols 0..7 = h part)
    const float* __restrict__ W_out,  // [OUT, HID]
    const float* __restrict__ b_out,  // [OUT]
    const float* __restrict__ wf,     // [NLAY, HID]
    const float* __restrict__ wi,
    const float* __restrict__ wg,
    const float* __restrict__ wo,
    float* __restrict__ out)          // [B, T, OUT]
{
    __shared__ float2 sCS2[4][NHID];   // (cos, sin) of 0.5*layer-2 weight

    const int tid = threadIdx.x;
    if (tid < 4 * NHID) {
        const float* wp[4] = {wf, wi, wg, wo};
        int g = tid / NHID;
        int w = tid % NHID;
        float s_, c_;
        sincosf(0.5f * wp[g][NHID + w], &s_, &c_);    // layer index 1
        sCS2[g][w] = make_float2(c_, s_);
    }
    __syncthreads();

    const unsigned FULL = 0xffffffffu;
    const int lane = tid & 31;
    const int b    = blockIdx.x * (blockDim.x >> 5) + (tid >> 5);  // element
    const int oct  = lane >> 3;            // gate id (f,i,g,o)
    const int q    = lane & 7;             // wire0,1,2 = q bits 2,1,0
    const int oct6 = oct * 6;              // broadcast base for merged angles

    const int ibx0 = (q >> 2) & 1;   // wire0 bit
    const int ibx1 = (q >> 1) & 1;   // wire1 bit
    const int ibx2 = q & 1;          // wire2 bit
    const bool bx0 = ibx0, bx2 = ibx2;

    // per-lane angle-row: lanes 0..23 = (gate = lane/6, wire = lane%6)
    const int gl = lane / 6;
    const int wlane = lane - 6 * gl;
    const bool aln = (lane < 24);

    // Hoisted weights
    float winh[8];
    float th2;
    {
        int row = aln ? wlane : 0;
        #pragma unroll
        for (int j = 0; j < 8; j++) winh[j] = W_in[row * NCAT + j];
        const float* wp[4] = {wf, wi, wg, wo};
        th2 = aln ? 0.5f * wp[gl][wlane] : 0.0f;     // layer index 0
    }
    // W_out row with deferred-butterfly signs premultiplied:
    //   wrow[0] *= s12, wrow[1] *= s01, wrow[2..5] *= s012
    float wrow[NHID];
    {
        float s01  = ((ibx0 + ibx1) & 1) ? -1.0f : 1.0f;
        float s12  = ((ibx1 + ibx2) & 1) ? -1.0f : 1.0f;
        float s012 = ((ibx0 + ibx1 + ibx2) & 1) ? -1.0f : 1.0f;
        wrow[0] = W_out[q * NHID + 0] * s12;
        wrow[1] = W_out[q * NHID + 1] * s01;
        wrow[2] = W_out[q * NHID + 2] * s012;
        wrow[3] = W_out[q * NHID + 3] * s012;
        wrow[4] = W_out[q * NHID + 4] * s012;
        wrow[5] = W_out[q * NHID + 5] * s012;
    }
    const float bj = b_out[q];

    // ring-1 folded phases: k(a) = popc(F^-1(y)) & 3. parity(k) == a0 always,
    // so only the sign is needed. Precompute packed sign constants per pack.
    unsigned long long sgn2[4];
    #pragma unroll
    for (int p = 0; p < 4; p++) {
        float sg[2];
        #pragma unroll
        for (int s = 0; s < 2; s++) {
            int a = 2 * p + s;
            int a0 = a & 1, a1 = (a >> 1) & 1, a2 = (a >> 2) & 1;
            int z0 = ibx0 ^ a0;
            int z1 = ibx1 ^ ibx0 ^ a0;
            int z2 = ibx2 ^ ibx1;
            int z3 = a2 ^ ibx2;
            int z4 = a1 ^ a2;
            int z5 = a0 ^ a1;
            int k = (z0 + z1 + z2 + z3 + z4 + z5) & 3;
            sg[s] = (k == 0 || k == 3) ? 1.0f : -1.0f;
        }
        sgn2[p] = pk2(sg[0], sg[1]);
    }
    const bool x01 = (ibx1 ^ ibx0) != 0;
    const bool x12 = (ibx2 ^ ibx1) != 0;

    // Layer-2 constants: wires 1..4 packed; wire 0 as packed rotors; wire 5
    // folded into probability constants A5 = c5^2, B5 = s5^2, K5 = 2 c5 s5.
    unsigned long long cc2[5], ss2[5], sn2[5];
    unsigned long long cs0pk, ns0pk;
    float A5, B5, K5;
    {
        #pragma unroll
        for (int w = 1; w < 5; w++) {
            float2 cs = sCS2[oct][w];
            cc2[w] = pk2(cs.x, cs.x);
            ss2[w] = pk2(cs.y, cs.y);
            sn2[w] = pk2(-cs.y, -cs.y);
        }
        float2 csw0 = sCS2[oct][0];
        cs0pk = pk2(csw0.x, csw0.y);    // (c0, s0)
        ns0pk = pk2(-csw0.y, csw0.x);   // (-s0, c0)
        float2 csw5 = sCS2[oct][5];
        A5 = csw5.x * csw5.x;
        B5 = csw5.y * csw5.y;
        K5 = 2.0f * csw5.x * csw5.y;
    }

    float* orow = out + (size_t)b * NT * NOUT;
    const float* prep = g_xpre + (size_t)b * NT * NHID;

    float h = 0.0f, c = 0.0f;
    float pre_cur = aln ? prep[wlane] : 0.0f;

    #pragma unroll 1
    for (int t = 0; t < NT; t++) {
        // ---- y = pre + W_h·h, merged half-angle = 0.5*y + th2 ----
        float y = pre_cur;
        #pragma unroll
        for (int j = 0; j < 8; j++) {
            float hj = __shfl_sync(FULL, h, j);
            y = fmaf(winh[j], hj, y);
        }
        float pre_nxt = 0.0f;
        if (t + 1 < NT && aln) pre_nxt = prep[(t + 1) * NHID + wlane];

        float myS, myC;
        __sincosf(fmaf(0.5f, y, th2), &myS, &myC);
        float cw[NHID], sw[NHID];
        #pragma unroll
        for (int w = 0; w < NHID; w++) {
            cw[w] = __shfl_sync(FULL, myC, oct6 + w);
            sw[w] = __shfl_sync(FULL, myS, oct6 + w);
        }

        // ---- post-ring-1 state, fully packed construct ----
        float F0_0 = bx0 ? sw[0] : cw[0];
        float F0_1 = bx0 ? cw[0] : sw[0];
        float F1_0 = x01 ? sw[1] : cw[1];
        float F1_1 = x01 ? cw[1] : sw[1];
        float f2v  = x12 ? sw[2] : cw[2];
        float G0 = F0_0 * F1_0 * f2v;          // a0 = 0 factor
        float G1 = F0_1 * F1_1 * f2v;          // a0 = 1 factor
        float F3_0 = bx2 ? sw[3] : cw[3];      // a2 = 0
        float F3_1 = bx2 ? cw[3] : sw[3];      // a2 = 1
        const float M00 = cw[4] * cw[5];
        const float M01 = cw[4] * sw[5];
        const float M10 = sw[4] * cw[5];
        const float M11 = sw[4] * sw[5];

        unsigned long long GG  = pk2(G0, G1);
        unsigned long long F3e = pk2(F3_0, F3_0);
        unsigned long long F3o = pk2(F3_1, F3_1);
        unsigned long long V[4];
        V[0] = mul2_(mul2_(GG, F3e), mul2_(pk2(M00, M01), sgn2[0]));
        V[1] = mul2_(mul2_(GG, F3e), mul2_(pk2(M11, M10), sgn2[1]));
        V[2] = mul2_(mul2_(GG, F3o), mul2_(pk2(M10, M11), sgn2[2]));
        V[3] = mul2_(mul2_(GG, F3o), mul2_(pk2(M01, M00), sgn2[3]));

        // ---- RX2 wire 0 (lane mask 4): sparse packed stage ----
        // R[p] = (c0,s0) ⊙ (v_lo, vp_hi);  I[p] = (-s0,c0) ⊙ (vp_lo, v_hi)
        unsigned long long R[4], I[4];
        #pragma unroll
        for (int p = 0; p < 4; p++) {
            unsigned long long Vx = __shfl_xor_sync(FULL, V[p], 4);
            float vl, vh, xl, xh;
            upk2(V[p], vl, vh);
            upk2(Vx, xl, xh);
            R[p] = mul2_(cs0pk, pk2(vl, xh));
            I[p] = mul2_(ns0pk, pk2(xl, vh));
        }

        // ---- RX2 wires 1,2 (lane masks 2,1), packed ----
        #pragma unroll
        for (int w = 1; w < 3; w++) {
            const int m = 4 >> w;
            unsigned long long Rp[4], Ip[4];
            #pragma unroll
            for (int p = 0; p < 4; p++) {
                Rp[p] = __shfl_xor_sync(FULL, R[p], m);
                Ip[p] = __shfl_xor_sync(FULL, I[p], m);
            }
            #pragma unroll
            for (int p = 0; p < 4; p++) {
                R[p] = fma2_(cc2[w], R[p], mul2_(ss2[w], Ip[p]));
                I[p] = fma2_(cc2[w], I[p], mul2_(sn2[w], Rp[p]));
            }
        }
        // ---- wires 3,4 (amp masks 4,2 -> pack partners ^2, ^1), packed ----
        #pragma unroll
        for (int w = 3; w < 5; w++) {
            const int pm = (w == 3) ? 2 : 1;
            unsigned long long nR[4], nI[4];
            #pragma unroll
            for (int p = 0; p < 4; p++) {
                nR[p] = fma2_(cc2[w], R[p], mul2_(ss2[w], I[p ^ pm]));
                nI[p] = fma2_(cc2[w], I[p], mul2_(sn2[w], R[p ^ pm]));
            }
            #pragma unroll
            for (int p = 0; p < 4; p++) { R[p] = nR[p]; I[p] = nI[p]; }
        }

        // ---- wire 5 folded into probabilities ----
        // n = |amp|^2 (packed); w_k = gr0*gi1 - gi0*gr1;
        // p[2k]   = A5*n0 + B5*n1 + K5*w_k
        // p[2k+1] = B5*n0 + A5*n1 - K5*w_k
        float p[8];
        #pragma unroll
        for (int k = 0; k < 4; k++) {
            unsigned long long N = fma2_(I[k], I[k], mul2_(R[k], R[k]));
            float n0, n1, r0, r1, i0, i1;
            upk2(N, n0, n1);
            upk2(R[k], r0, r1);
            upk2(I[k], i0, i1);
            float wk = fmaf(r0, i1, -(i0 * r1));
            float tk = K5 * wk;
            p[2 * k]     = fmaf(A5, n0, fmaf(B5, n1, tk));
            p[2 * k + 1] = fmaf(B5, n0, fmaf(A5, n1, -tk));
        }

        // ---- expvals: deferred-sign butterflies (signs in wrow) ----
        float acc;
        {
            float t01 = p[0] + p[1], t23 = p[2] + p[3];
            float t45 = p[4] + p[5], t67 = p[6] + p[7];
            float slo = t01 + t23, shi = t45 + t67;
            float uA  = slo + shi;
            float u3  = slo - shi;
            float u4  = (t01 + t67) - (t23 + t45);
            float u5  = ((p[0] + p[3]) + (p[5] + p[6]))
                      - ((p[1] + p[2]) + (p[4] + p[7]));

            // stage 1 (A,A3,A4: mask4; A5: mask2)
            float tA = __shfl_xor_sync(FULL, uA, 4);
            float t3 = __shfl_xor_sync(FULL, u3, 4);
            float t4 = __shfl_xor_sync(FULL, u4, 4);
            float t5 = __shfl_xor_sync(FULL, u5, 2);
            uA -= tA; u3 -= t3; u4 -= t4; u5 -= t5;
            // stage 2 (A,A3,A4: mask2; A5: mask1)
            tA = __shfl_xor_sync(FULL, uA, 2);
            t3 = __shfl_xor_sync(FULL, u3, 2);
            t4 = __shfl_xor_sync(FULL, u4, 2);
            t5 = __shfl_xor_sync(FULL, u5, 1);
            uA -= tA; u3 -= t3; u4 -= t4; u5 -= t5;
            // stage 3 (A,A3,A4: mask1; A5: mask4)
            tA = __shfl_xor_sync(FULL, uA, 1);
            t3 = __shfl_xor_sync(FULL, u3, 1);
            t4 = __shfl_xor_sync(FULL, u4, 1);
            t5 = __shfl_xor_sync(FULL, u5, 4);
            float E1 = uA + tA;       // * s01   (in wrow[1])
            float E2 = uA - tA;       // * s012  (in wrow[2])
            float E3 = u3 - t3;       // * s012
            float E4 = u4 - t4;       // * s012
            float E0 = u5 + t5;       // * s12   (in wrow[0])
            float E5 = u5 - t5;       // * s012

            acc = bj;
            acc = fmaf(wrow[0], E0, acc);
            acc = fmaf(wrow[1], E1, acc);
            acc = fmaf(wrow[2], E2, acc);
            acc = fmaf(wrow[3], E3, acc);
            acc = fmaf(wrow[4], E4, acc);
            acc = fmaf(wrow[5], E5, acc);
        }

        // ---- gather all 4 gates for dim q ----
        float af = __shfl_sync(FULL, acc, q);        // octet 0 = f
        float ai = __shfl_sync(FULL, acc, 8 | q);    // octet 1 = i
        float ag = __shfl_sync(FULL, acc, 16 | q);   // octet 2 = g
        float ao = __shfl_sync(FULL, acc, 24 | q);   // octet 3 = o

        float fg = sigmoidf_(af);
        float ig = sigmoidf_(ai);
        float gg = tanhfast_(ag);
        float og = sigmoidf_(ao);
        c = fmaf(fg, c, ig * gg);
        h = og * tanhfast_(c);

        if (lane < NOUT) orow[t * NOUT + q] = h;
        pre_cur = pre_nxt;
    }
}

extern "C" void kernel_launch(void* const* d_in, const int* in_sizes, int n_in,
                              void* d_out, int out_size) {
    (void)in_sizes; (void)n_in; (void)out_size;
    xpre_kernel<<<(NB * NT + 255) / 256, 256>>>(
        (const float*)d_in[0],   // x
        (const float*)d_in[1],   // W_in
        (const float*)d_in[2]);  // b_in
    // 1 element/warp, 4 warps/block -> 512 blocks, 2048 warps
    qlstm_kernel<<<NB / 4, 128>>>(
        (const float*)d_in[1],   // W_in (h part)
        (const float*)d_in[3],   // W_out
        (const float*)d_in[4],   // b_out
        (const float*)d_in[5],   // wf
        (const float*)d_in[6],   // wi
        (const float*)d_in[7],   // wg
        (const float*)d_in[8],   // wo
        (float*)d_out);
}